// round 4
// baseline (speedup 1.0000x reference)
#include <cuda_runtime.h>
#include <stdint.h>

#define NROWS   131072
#define DIM     128
#define QSTAGES 4
#define KCB     1024
#define BETA    0.25

typedef unsigned long long u64;
#define UMAX64 0xFFFFFFFFFFFFFFFFull

// Scratch (allocation-free rule: __device__ globals)
__device__ float  g_resid[NROWS * DIM];
__device__ float  g_enorm[QSTAGES * KCB];
__device__ double g_loss[QSTAGES];

// ---------------------------------------------------------------------------
// packed fp32x2 helpers (Blackwell sm_100+)
// ---------------------------------------------------------------------------
__device__ __forceinline__ u64 pack2f(float lo, float hi) {
    u64 r; asm("mov.b64 %0, {%1, %2};" : "=l"(r) : "f"(lo), "f"(hi)); return r;
}
__device__ __forceinline__ void unpack2f(u64 v, float& lo, float& hi) {
    asm("mov.b64 {%0, %1}, %2;" : "=f"(lo), "=f"(hi) : "l"(v));
}
__device__ __forceinline__ void ffma2(u64& d, u64 a, u64 b) {
    asm("fma.rn.f32x2 %0, %1, %2, %0;" : "+l"(d) : "l"(a), "l"(b));
}
__device__ __forceinline__ unsigned int fkey(float f) {
    unsigned int u = __float_as_uint(f);
    return (u & 0x80000000u) ? ~u : (u | 0x80000000u);
}
__device__ __forceinline__ void top2(u64 k, u64& b0, u64& b1) {
    if (k < b0) { b1 = b0; b0 = k; }
    else if (k < b1) { b1 = k; }
}

// ---------------------------------------------------------------------------
__global__ void rvq_prep_kernel(const float* __restrict__ cb) {
    if (blockIdx.x == 0 && threadIdx.x < QSTAGES) g_loss[threadIdx.x] = 0.0;
    int wid  = (blockIdx.x * blockDim.x + threadIdx.x) >> 5;
    int lane = threadIdx.x & 31;
    if (wid >= QSTAGES * KCB) return;
    const float* row = cb + (size_t)wid * DIM;
    double s = 0.0;
#pragma unroll
    for (int i = 0; i < 4; i++) {
        double v = (double)row[lane + i * 32];
        s = fma(v, v, s);
    }
#pragma unroll
    for (int off = 16; off; off >>= 1) s += __shfl_down_sync(0xffffffffu, s, off);
    if (lane == 0) g_enorm[wid] = (float)s;
}

// ---------------------------------------------------------------------------
// One RVQ stage. 256 threads, 128x128 tile, 8x8 microtile via fp32x2 FMA.
// Double-buffered smem (1 sync/chunk). B stored pre-duplicated as u64 pairs
// so the inner loop is pure LDS.128 + FFMA2 (no pack movs).
// ---------------------------------------------------------------------------
template <int STAGE>
__global__ __launch_bounds__(256, 2)
void rvq_stage_kernel(const float* __restrict__ x,
                      const float* __restrict__ cbq,
                      float* __restrict__ out)
{
    const float* cb  = cbq + (size_t)STAGE * KCB * DIM;
    const float* rin = (STAGE == 0) ? x : (const float*)g_resid;

    __shared__ __align__(16) float As[2][8][132];   //  8.4 KB
    __shared__ __align__(16) u64   BsD[2][8][132];  // 16.9 KB (duplicated pairs)
    __shared__ u64   Red[128][17];                  // 17.4 KB (two-pass reduce)
    __shared__ float rrS[128];
    __shared__ int   Ridx[128];
    __shared__ int   Ridx2[128];

    const int tid = threadIdx.x;
    const int m0  = blockIdx.x * 128;
    const int tx  = tid & 15;
    const int ty  = tid >> 4;
    const int lm  = tid >> 1;
    const int ld  = (tid & 1) * 4;

    // ---- pre-pass: rr per row (double, correctly rounded) ----
    {
        const int row = tid >> 1;
        const int h   = (tid & 1) * 64;
        const float* rv = rin + (size_t)(m0 + row) * DIM + h;
        double s = 0.0;
#pragma unroll
        for (int c = 0; c < 16; c++) {
            float4 v = *(const float4*)(rv + c * 4);
            s = fma((double)v.x, (double)v.x, s);
            s = fma((double)v.y, (double)v.y, s);
            s = fma((double)v.z, (double)v.z, s);
            s = fma((double)v.w, (double)v.w, s);
        }
        s += __shfl_xor_sync(0xffffffffu, s, 1);
        if ((tid & 1) == 0) rrS[row] = (float)s;
    }
    __syncthreads();

    float rrv[8];
#pragma unroll
    for (int i = 0; i < 8; i++) rrv[i] = rrS[ty * 8 + i];

    u64 best0 = UMAX64, best1 = UMAX64;   // running global top2 (tid<128: row=tid)

    const float* aBase = rin + (size_t)(m0 + lm) * DIM + ld;

    for (int nt = 0; nt < KCB / 128; nt++) {
        const int n0 = nt * 128;
        u64 acc2[4][8];
#pragma unroll
        for (int p = 0; p < 4; p++)
#pragma unroll
            for (int j = 0; j < 8; j++) acc2[p][j] = 0ull;

        const float* bBase = cb + (size_t)(n0 + lm) * DIM + ld;

        // preload chunk 0 into buffer 0
        {
            float4 a0 = *(const float4*)(aBase);
            float4 b0 = *(const float4*)(bBase);
            As[0][ld + 0][lm] = a0.x; As[0][ld + 1][lm] = a0.y;
            As[0][ld + 2][lm] = a0.z; As[0][ld + 3][lm] = a0.w;
            BsD[0][ld + 0][lm] = pack2f(b0.x, b0.x);
            BsD[0][ld + 1][lm] = pack2f(b0.y, b0.y);
            BsD[0][ld + 2][lm] = pack2f(b0.z, b0.z);
            BsD[0][ld + 3][lm] = pack2f(b0.w, b0.w);
        }
        __syncthreads();

#pragma unroll 1
        for (int ds = 0; ds < 16; ds++) {
            const int cur = ds & 1, nxt = cur ^ 1;
            float4 an, bn;
            if (ds < 15) {
                an = *(const float4*)(aBase + (ds + 1) * 8);
                bn = *(const float4*)(bBase + (ds + 1) * 8);
            }
#pragma unroll
            for (int dd = 0; dd < 8; dd++) {
                const u64* aP = (const u64*)&As[cur][dd][ty * 8];
                ulonglong2 aL = *(const ulonglong2*)(aP);
                ulonglong2 aH = *(const ulonglong2*)(aP + 2);
                u64 a2[4] = { aL.x, aL.y, aH.x, aH.y };
                const u64* bP = &BsD[cur][dd][tx * 8];
                ulonglong2 b01 = *(const ulonglong2*)(bP);
                ulonglong2 b23 = *(const ulonglong2*)(bP + 2);
                ulonglong2 b45 = *(const ulonglong2*)(bP + 4);
                ulonglong2 b67 = *(const ulonglong2*)(bP + 6);
                u64 bb[8] = { b01.x, b01.y, b23.x, b23.y,
                              b45.x, b45.y, b67.x, b67.y };
#pragma unroll
                for (int p = 0; p < 4; p++)
#pragma unroll
                    for (int j = 0; j < 8; j++)
                        ffma2(acc2[p][j], a2[p], bb[j]);
            }
            if (ds < 15) {
                As[nxt][ld + 0][lm] = an.x; As[nxt][ld + 1][lm] = an.y;
                As[nxt][ld + 2][lm] = an.z; As[nxt][ld + 3][lm] = an.w;
                BsD[nxt][ld + 0][lm] = pack2f(bn.x, bn.x);
                BsD[nxt][ld + 1][lm] = pack2f(bn.y, bn.y);
                BsD[nxt][ld + 2][lm] = pack2f(bn.z, bn.z);
                BsD[nxt][ld + 3][lm] = pack2f(bn.w, bn.w);
                __syncthreads();
            }
        }

        // ---- tile argmin: scores replicate reference ((rr - 2*dot) + ee) ----
        float en[8];
#pragma unroll
        for (int j = 0; j < 8; j++) en[j] = __ldg(&g_enorm[STAGE * KCB + n0 + tx * 8 + j]);

        u64 pb0[8], pb1[8];
#pragma unroll
        for (int p = 0; p < 4; p++) {
            const int r0 = 2 * p;
            u64 x0 = UMAX64, x1 = UMAX64, y0 = UMAX64, y1 = UMAX64;
#pragma unroll
            for (int j = 0; j < 8; j++) {
                float dlo, dhi;
                unpack2f(acc2[p][j], dlo, dhi);
                float slo = (rrv[r0]     - 2.0f * dlo) + en[j];
                float shi = (rrv[r0 + 1] - 2.0f * dhi) + en[j];
                unsigned idx = (unsigned)(n0 + tx * 8 + j);
                top2(((u64)fkey(slo) << 32) | idx, x0, x1);
                top2(((u64)fkey(shi) << 32) | idx, y0, y1);
            }
            pb0[r0] = x0; pb1[r0] = x1;
            pb0[r0 + 1] = y0; pb1[r0 + 1] = y1;
        }

        // pass 1: per-stripe top1s -> exact global top1 t0 + 2nd-min-of-b0s t1
        __syncthreads();   // all threads past reading Red from prior tile
#pragma unroll
        for (int i = 0; i < 8; i++) Red[ty * 8 + i][tx] = pb0[i];
        __syncthreads();
        u64 t0 = UMAX64, t1 = UMAX64; int sstar = 0;
        if (tid < 128) {
#pragma unroll
            for (int t = 0; t < 16; t++) top2(Red[tid][t], t0, t1);
            sstar = (int)((t0 & 127u) >> 3);   // winner stripe (tx)
        }
        __syncthreads();
        // pass 2: per-stripe runner-ups; exact top2 = min(t1, b1[winner stripe])
#pragma unroll
        for (int i = 0; i < 8; i++) Red[ty * 8 + i][tx] = pb1[i];
        __syncthreads();
        if (tid < 128) {
            u64 w = Red[tid][sstar];
            if (w < t1) t1 = w;
            top2(t0, best0, best1);
            top2(t1, best0, best1);
        }
    }

    __syncthreads();
    if (tid < 128) {
        Ridx[tid]  = (int)(best0 & 0xFFFFFFFFull);
        Ridx2[tid] = (int)(best1 & 0xFFFFFFFFull);
    }
    __syncthreads();

    // ---- double-precision rescue + residual update + loss ----
    const int row = tid >> 1;
    const int h   = (tid & 1) * 64;
    const int i1  = Ridx[row];
    const int i2  = Ridx2[row];
    const float* rv = rin + (size_t)(m0 + row) * DIM + h;
    const float* e1 = cb + (size_t)i1 * DIM + h;
    const float* e2 = cb + (size_t)i2 * DIM + h;

    double d1 = 0.0, d2 = 0.0;
#pragma unroll
    for (int c = 0; c < 16; c++) {
        float4 r4 = *(const float4*)(rv + c * 4);
        float4 q1 = *(const float4*)(e1 + c * 4);
        float4 q2 = *(const float4*)(e2 + c * 4);
        d1 = fma((double)r4.x, (double)q1.x, d1);
        d1 = fma((double)r4.y, (double)q1.y, d1);
        d1 = fma((double)r4.z, (double)q1.z, d1);
        d1 = fma((double)r4.w, (double)q1.w, d1);
        d2 = fma((double)r4.x, (double)q2.x, d2);
        d2 = fma((double)r4.y, (double)q2.y, d2);
        d2 = fma((double)r4.z, (double)q2.z, d2);
        d2 = fma((double)r4.w, (double)q2.w, d2);
    }
    d1 += __shfl_xor_sync(0xffffffffu, d1, 1);
    d2 += __shfl_xor_sync(0xffffffffu, d2, 1);

    const float rr = rrS[row];
    const float s1 = (rr - 2.0f * (float)d1) + __ldg(&g_enorm[STAGE * KCB + i1]);
    const float s2 = (rr - 2.0f * (float)d2) + __ldg(&g_enorm[STAGE * KCB + i2]);
    int cidx;
    if (s1 < s2)      cidx = i1;
    else if (s2 < s1) cidx = i2;
    else              cidx = (i1 < i2) ? i1 : i2;

    if ((tid & 1) == 0)
        out[(size_t)NROWS * DIM + 1 + (size_t)(m0 + row) * QSTAGES + STAGE] = (float)cidx;

    const float* qv = cb + (size_t)cidx * DIM + h;
    double lsum = 0.0;
#pragma unroll
    for (int c = 0; c < 16; c++) {
        float4 q = *(const float4*)(qv + c * 4);
        float4 r = *(const float4*)(rv + c * 4);
        float4 rn;
        rn.x = r.x - q.x; rn.y = r.y - q.y; rn.z = r.z - q.z; rn.w = r.w - q.w;
        lsum += (double)rn.x * rn.x + (double)rn.y * rn.y +
                (double)rn.z * rn.z + (double)rn.w * rn.w;
        if (STAGE < QSTAGES - 1) {
            *(float4*)(g_resid + (size_t)(m0 + row) * DIM + h + c * 4) = rn;
        } else {
            const float4 xx = *(const float4*)(x + (size_t)(m0 + row) * DIM + h + c * 4);
            float4 xq;
            xq.x = xx.x - rn.x; xq.y = xx.y - rn.y;
            xq.z = xx.z - rn.z; xq.w = xx.w - rn.w;
            *(float4*)(out + (size_t)(m0 + row) * DIM + h + c * 4) = xq;
        }
    }
#pragma unroll
    for (int off = 16; off; off >>= 1) lsum += __shfl_down_sync(0xffffffffu, lsum, off);
    if ((tid & 31) == 0) atomicAdd(&g_loss[STAGE], lsum);
}

// ---------------------------------------------------------------------------
__global__ void rvq_finalize_kernel(float* __restrict__ out) {
    if (threadIdx.x == 0) {
        double s = 0.0;
        for (int i = 0; i < QSTAGES; i++) s += g_loss[i];
        double mean = (1.0 + BETA) * s / ((double)NROWS * DIM) / (double)QSTAGES;
        out[(size_t)NROWS * DIM] = (float)mean;
    }
}

extern "C" void kernel_launch(void* const* d_in, const int* in_sizes, int n_in,
                              void* d_out, int out_size) {
    const float* x  = (const float*)d_in[0];
    const float* cb = (const float*)d_in[1];
    if (n_in >= 2 && in_sizes[0] == QSTAGES * KCB * DIM && in_sizes[1] == NROWS * DIM) {
        x  = (const float*)d_in[1];
        cb = (const float*)d_in[0];
    }
    float* out = (float*)d_out;

    rvq_prep_kernel<<<512, 256>>>(cb);
    rvq_stage_kernel<0><<<NROWS / 128, 256>>>(x, cb, out);
    rvq_stage_kernel<1><<<NROWS / 128, 256>>>(x, cb, out);
    rvq_stage_kernel<2><<<NROWS / 128, 256>>>(x, cb, out);
    rvq_stage_kernel<3><<<NROWS / 128, 256>>>(x, cb, out);
    rvq_finalize_kernel<<<1, 32>>>(out);
}

// round 5
// speedup vs baseline: 1.9221x; 1.9221x over previous
#include <cuda_runtime.h>
#include <stdint.h>

#define NROWS   131072
#define DIM     128
#define QSTAGES 4
#define KCB     1024
#define BETA    0.25

typedef unsigned long long u64;
#define UMAX64 0xFFFFFFFFFFFFFFFFull

// Scratch (allocation-free rule: __device__ globals)
__device__ float  g_resid[NROWS * DIM];
__device__ float  g_enorm[QSTAGES * KCB];
__device__ double g_loss[QSTAGES];

// ---------------------------------------------------------------------------
// packed fp32x2 helpers (Blackwell sm_100+)
// ---------------------------------------------------------------------------
__device__ __forceinline__ u64 pack2f(float lo, float hi) {
    u64 r; asm("mov.b64 %0, {%1, %2};" : "=l"(r) : "f"(lo), "f"(hi)); return r;
}
__device__ __forceinline__ void unpack2f(u64 v, float& lo, float& hi) {
    asm("mov.b64 {%0, %1}, %2;" : "=f"(lo), "=f"(hi) : "l"(v));
}
__device__ __forceinline__ void ffma2(u64& d, u64 a, u64 b) {
    asm("fma.rn.f32x2 %0, %1, %2, %0;" : "+l"(d) : "l"(a), "l"(b));
}
__device__ __forceinline__ unsigned int fkey(float f) {
    unsigned int u = __float_as_uint(f);
    return (u & 0x80000000u) ? ~u : (u | 0x80000000u);
}
__device__ __forceinline__ void top2(u64 k, u64& b0, u64& b1) {
    if (k < b0) { b1 = b0; b0 = k; }
    else if (k < b1) { b1 = k; }
}

// ---------------------------------------------------------------------------
__global__ void rvq_prep_kernel(const float* __restrict__ cb) {
    if (blockIdx.x == 0 && threadIdx.x < QSTAGES) g_loss[threadIdx.x] = 0.0;
    int wid  = (blockIdx.x * blockDim.x + threadIdx.x) >> 5;
    int lane = threadIdx.x & 31;
    if (wid >= QSTAGES * KCB) return;
    const float* row = cb + (size_t)wid * DIM;
    double s = 0.0;
#pragma unroll
    for (int i = 0; i < 4; i++) {
        double v = (double)row[lane + i * 32];
        s = fma(v, v, s);
    }
#pragma unroll
    for (int off = 16; off; off >>= 1) s += __shfl_down_sync(0xffffffffu, s, off);
    if (lane == 0) g_enorm[wid] = (float)s;
}

// ---------------------------------------------------------------------------
// One RVQ stage. 256 threads, 128x128 tile, 8x8 microtile via fp32x2 FMA.
// Warp = 4 row-groups x 8 cw-groups. Smem fragments are chunk-interleaved at
// 16B granularity so every consumer LDS.128 reads lane-consecutive 16B units
// (conflict-free, broadcast-deduped). B pre-duplicated as u64 pairs: the
// inner loop is pure LDS.128 + FFMA2. Double-buffered, 1 sync per chunk.
// ---------------------------------------------------------------------------
template <int STAGE>
__global__ __launch_bounds__(256, 2)
void rvq_stage_kernel(const float* __restrict__ x,
                      const float* __restrict__ cbq,
                      float* __restrict__ out)
{
    const float* cb  = cbq + (size_t)STAGE * KCB * DIM;
    const float* rin = (STAGE == 0) ? x : (const float*)g_resid;

    // [buf][dd][chunk][group] -> 16B units, lane-consecutive per chunk
    __shared__ __align__(16) float4     AsI[2][8][2][16];   //  8 KB
    __shared__ __align__(16) ulonglong2 BsI[2][8][4][16];   // 16 KB (dup pairs)
    __shared__ u64   Red[128][17];                          // 17.4 KB
    __shared__ float rrS[128];
    __shared__ int   Ridx[128];
    __shared__ int   Ridx2[128];

    const int tid  = threadIdx.x;
    const int m0   = blockIdx.x * 128;
    const int lane = tid & 31;
    const int wrp  = tid >> 5;
    // warp covers 4 ty x 8 tx
    const int tx = (lane & 7) | ((wrp & 1) << 3);    // cw-group  0..15
    const int ty = (lane >> 3) | ((wrp >> 1) << 2);  // row-group 0..15
    const int lm = tid >> 1;                         // loader row 0..127
    const int ld = (tid & 1) * 4;                    // loader dim offset {0,4}

    // ---- pre-pass: rr per row (double, correctly rounded) ----
    {
        const int row = tid >> 1;
        const int h   = (tid & 1) * 64;
        const float* rv = rin + (size_t)(m0 + row) * DIM + h;
        double s = 0.0;
#pragma unroll
        for (int c = 0; c < 16; c++) {
            float4 v = *(const float4*)(rv + c * 4);
            s = fma((double)v.x, (double)v.x, s);
            s = fma((double)v.y, (double)v.y, s);
            s = fma((double)v.z, (double)v.z, s);
            s = fma((double)v.w, (double)v.w, s);
        }
        s += __shfl_xor_sync(0xffffffffu, s, 1);
        if ((tid & 1) == 0) rrS[row] = (float)s;
    }
    __syncthreads();

    float rrv[8];
#pragma unroll
    for (int i = 0; i < 8; i++) rrv[i] = rrS[ty * 8 + i];

    u64 best0 = UMAX64, best1 = UMAX64;   // running global top2 (tid<128: row=tid)

    const float* aBase = rin + (size_t)(m0 + lm) * DIM + ld;
    const int aty = lm >> 3, ac = (lm & 7) >> 2, ap = lm & 3;   // A store slot
    const int btx = lm >> 3, bc = (lm & 7) >> 1, bp = lm & 1;   // B store slot

    for (int nt = 0; nt < KCB / 128; nt++) {
        const int n0 = nt * 128;
        u64 acc2[4][8];
#pragma unroll
        for (int p = 0; p < 4; p++)
#pragma unroll
            for (int j = 0; j < 8; j++) acc2[p][j] = 0ull;

        const float* bBase = cb + (size_t)(n0 + lm) * DIM + ld;

        // preload chunk 0 into buffer 0
        {
            float4 a0 = *(const float4*)(aBase);
            float4 b0 = *(const float4*)(bBase);
            const float av[4] = { a0.x, a0.y, a0.z, a0.w };
            const float bv[4] = { b0.x, b0.y, b0.z, b0.w };
#pragma unroll
            for (int k = 0; k < 4; k++) {
                ((float*)&AsI[0][ld + k][ac][aty])[ap] = av[k];
                ((u64*)  &BsI[0][ld + k][bc][btx])[bp] = pack2f(bv[k], bv[k]);
            }
        }
        __syncthreads();

#pragma unroll 1
        for (int ds = 0; ds < 16; ds++) {
            const int cur = ds & 1, nxt = cur ^ 1;
            float4 an, bn;
            if (ds < 15) {
                an = *(const float4*)(aBase + (ds + 1) * 8);
                bn = *(const float4*)(bBase + (ds + 1) * 8);
            }
#pragma unroll
            for (int dd = 0; dd < 8; dd++) {
                ulonglong2 aL = *(const ulonglong2*)&AsI[cur][dd][0][ty];
                ulonglong2 aH = *(const ulonglong2*)&AsI[cur][dd][1][ty];
                u64 a2[4] = { aL.x, aL.y, aH.x, aH.y };
                ulonglong2 b01 = BsI[cur][dd][0][tx];
                ulonglong2 b23 = BsI[cur][dd][1][tx];
                ulonglong2 b45 = BsI[cur][dd][2][tx];
                ulonglong2 b67 = BsI[cur][dd][3][tx];
                u64 bb[8] = { b01.x, b01.y, b23.x, b23.y,
                              b45.x, b45.y, b67.x, b67.y };
#pragma unroll
                for (int p = 0; p < 4; p++)
#pragma unroll
                    for (int j = 0; j < 8; j++)
                        ffma2(acc2[p][j], a2[p], bb[j]);
            }
            if (ds < 15) {
                const float av[4] = { an.x, an.y, an.z, an.w };
                const float bv[4] = { bn.x, bn.y, bn.z, bn.w };
#pragma unroll
                for (int k = 0; k < 4; k++) {
                    ((float*)&AsI[nxt][ld + k][ac][aty])[ap] = av[k];
                    ((u64*)  &BsI[nxt][ld + k][bc][btx])[bp] = pack2f(bv[k], bv[k]);
                }
                __syncthreads();
            }
        }

        // ---- tile argmin: scores replicate reference ((rr - 2*dot) + ee) ----
        float en[8];
#pragma unroll
        for (int j = 0; j < 8; j++) en[j] = __ldg(&g_enorm[STAGE * KCB + n0 + tx * 8 + j]);

        u64 pb0[8], pb1[8];
#pragma unroll
        for (int p = 0; p < 4; p++) {
            const int r0 = 2 * p;
            u64 x0 = UMAX64, x1 = UMAX64, y0 = UMAX64, y1 = UMAX64;
#pragma unroll
            for (int j = 0; j < 8; j++) {
                float dlo, dhi;
                unpack2f(acc2[p][j], dlo, dhi);
                float slo = (rrv[r0]     - 2.0f * dlo) + en[j];
                float shi = (rrv[r0 + 1] - 2.0f * dhi) + en[j];
                unsigned idx = (unsigned)(n0 + tx * 8 + j);
                top2(((u64)fkey(slo) << 32) | idx, x0, x1);
                top2(((u64)fkey(shi) << 32) | idx, y0, y1);
            }
            pb0[r0] = x0; pb1[r0] = x1;
            pb0[r0 + 1] = y0; pb1[r0 + 1] = y1;
        }

        // pass 1: per-stripe top1s -> exact global top1 t0 + 2nd-min-of-b0s t1
        __syncthreads();   // all threads past reading Red from prior tile
#pragma unroll
        for (int i = 0; i < 8; i++) Red[ty * 8 + i][tx] = pb0[i];
        __syncthreads();
        u64 t0 = UMAX64, t1 = UMAX64; int sstar = 0;
        if (tid < 128) {
#pragma unroll
            for (int t = 0; t < 16; t++) top2(Red[tid][t], t0, t1);
            sstar = (int)((t0 & 127u) >> 3);   // winner stripe (tx)
        }
        __syncthreads();
        // pass 2: per-stripe runner-ups; exact top2 = min(t1, b1[winner stripe])
#pragma unroll
        for (int i = 0; i < 8; i++) Red[ty * 8 + i][tx] = pb1[i];
        __syncthreads();
        if (tid < 128) {
            u64 w = Red[tid][sstar];
            if (w < t1) t1 = w;
            top2(t0, best0, best1);
            top2(t1, best0, best1);
        }
    }

    __syncthreads();
    if (tid < 128) {
        Ridx[tid]  = (int)(best0 & 0xFFFFFFFFull);
        Ridx2[tid] = (int)(best1 & 0xFFFFFFFFull);
    }
    __syncthreads();

    // ---- double-precision rescue + residual update + loss ----
    const int row = tid >> 1;
    const int h   = (tid & 1) * 64;
    const int i1  = Ridx[row];
    const int i2  = Ridx2[row];
    const float* rv = rin + (size_t)(m0 + row) * DIM + h;
    const float* e1 = cb + (size_t)i1 * DIM + h;
    const float* e2 = cb + (size_t)i2 * DIM + h;

    double d1 = 0.0, d2 = 0.0;
#pragma unroll
    for (int c = 0; c < 16; c++) {
        float4 r4 = *(const float4*)(rv + c * 4);
        float4 q1 = *(const float4*)(e1 + c * 4);
        float4 q2 = *(const float4*)(e2 + c * 4);
        d1 = fma((double)r4.x, (double)q1.x, d1);
        d1 = fma((double)r4.y, (double)q1.y, d1);
        d1 = fma((double)r4.z, (double)q1.z, d1);
        d1 = fma((double)r4.w, (double)q1.w, d1);
        d2 = fma((double)r4.x, (double)q2.x, d2);
        d2 = fma((double)r4.y, (double)q2.y, d2);
        d2 = fma((double)r4.z, (double)q2.z, d2);
        d2 = fma((double)r4.w, (double)q2.w, d2);
    }
    d1 += __shfl_xor_sync(0xffffffffu, d1, 1);
    d2 += __shfl_xor_sync(0xffffffffu, d2, 1);

    const float rr = rrS[row];
    const float s1 = (rr - 2.0f * (float)d1) + __ldg(&g_enorm[STAGE * KCB + i1]);
    const float s2 = (rr - 2.0f * (float)d2) + __ldg(&g_enorm[STAGE * KCB + i2]);
    int cidx;
    if (s1 < s2)      cidx = i1;
    else if (s2 < s1) cidx = i2;
    else              cidx = (i1 < i2) ? i1 : i2;

    if ((tid & 1) == 0)
        out[(size_t)NROWS * DIM + 1 + (size_t)(m0 + row) * QSTAGES + STAGE] = (float)cidx;

    const float* qv = cb + (size_t)cidx * DIM + h;
    double lsum = 0.0;
#pragma unroll
    for (int c = 0; c < 16; c++) {
        float4 q = *(const float4*)(qv + c * 4);
        float4 r = *(const float4*)(rv + c * 4);
        float4 rn;
        rn.x = r.x - q.x; rn.y = r.y - q.y; rn.z = r.z - q.z; rn.w = r.w - q.w;
        lsum += (double)rn.x * rn.x + (double)rn.y * rn.y +
                (double)rn.z * rn.z + (double)rn.w * rn.w;
        if (STAGE < QSTAGES - 1) {
            *(float4*)(g_resid + (size_t)(m0 + row) * DIM + h + c * 4) = rn;
        } else {
            const float4 xx = *(const float4*)(x + (size_t)(m0 + row) * DIM + h + c * 4);
            float4 xq;
            xq.x = xx.x - rn.x; xq.y = xx.y - rn.y;
            xq.z = xx.z - rn.z; xq.w = xx.w - rn.w;
            *(float4*)(out + (size_t)(m0 + row) * DIM + h + c * 4) = xq;
        }
    }
#pragma unroll
    for (int off = 16; off; off >>= 1) lsum += __shfl_down_sync(0xffffffffu, lsum, off);
    if ((tid & 31) == 0) atomicAdd(&g_loss[STAGE], lsum);
}

// ---------------------------------------------------------------------------
__global__ void rvq_finalize_kernel(float* __restrict__ out) {
    if (threadIdx.x == 0) {
        double s = 0.0;
        for (int i = 0; i < QSTAGES; i++) s += g_loss[i];
        double mean = (1.0 + BETA) * s / ((double)NROWS * DIM) / (double)QSTAGES;
        out[(size_t)NROWS * DIM] = (float)mean;
    }
}

extern "C" void kernel_launch(void* const* d_in, const int* in_sizes, int n_in,
                              void* d_out, int out_size) {
    const float* x  = (const float*)d_in[0];
    const float* cb = (const float*)d_in[1];
    if (n_in >= 2 && in_sizes[0] == QSTAGES * KCB * DIM && in_sizes[1] == NROWS * DIM) {
        x  = (const float*)d_in[1];
        cb = (const float*)d_in[0];
    }
    float* out = (float*)d_out;

    rvq_prep_kernel<<<512, 256>>>(cb);
    rvq_stage_kernel<0><<<NROWS / 128, 256>>>(x, cb, out);
    rvq_stage_kernel<1><<<NROWS / 128, 256>>>(x, cb, out);
    rvq_stage_kernel<2><<<NROWS / 128, 256>>>(x, cb, out);
    rvq_stage_kernel<3><<<NROWS / 128, 256>>>(x, cb, out);
    rvq_finalize_kernel<<<1, 32>>>(out);
}

// round 6
// speedup vs baseline: 2.0290x; 1.0556x over previous
#include <cuda_runtime.h>
#include <stdint.h>

#define NROWS   131072
#define DIM     128
#define QSTAGES 4
#define KCB     1024
#define BETA    0.25
#define BROWS   256            // rows per block
#define NTHR    512

typedef unsigned long long u64;
#define UMAX64 0xFFFFFFFFFFFFFFFFull

// Scratch (allocation-free rule: __device__ globals)
__device__ float  g_resid[NROWS * DIM];
__device__ float  g_enorm[QSTAGES * KCB];
__device__ double g_loss[QSTAGES];

// ---------------------------------------------------------------------------
// packed fp32x2 helpers (Blackwell sm_100+)
// ---------------------------------------------------------------------------
__device__ __forceinline__ u64 pack2f(float lo, float hi) {
    u64 r; asm("mov.b64 %0, {%1, %2};" : "=l"(r) : "f"(lo), "f"(hi)); return r;
}
__device__ __forceinline__ void unpack2f(u64 v, float& lo, float& hi) {
    asm("mov.b64 {%0, %1}, %2;" : "=f"(lo), "=f"(hi) : "l"(v));
}
__device__ __forceinline__ void ffma2(u64& d, u64 a, u64 b) {
    asm("fma.rn.f32x2 %0, %1, %2, %0;" : "+l"(d) : "l"(a), "l"(b));
}
__device__ __forceinline__ unsigned int fkey(float f) {
    unsigned int u = __float_as_uint(f);
    return (u & 0x80000000u) ? ~u : (u | 0x80000000u);
}
__device__ __forceinline__ void top2(u64 k, u64& b0, u64& b1) {
    if (k < b0) { b1 = b0; b0 = k; }
    else if (k < b1) { b1 = k; }
}

// ---------------------------------------------------------------------------
__global__ void rvq_prep_kernel(const float* __restrict__ cb) {
    if (blockIdx.x == 0 && threadIdx.x < QSTAGES) g_loss[threadIdx.x] = 0.0;
    int wid  = (blockIdx.x * blockDim.x + threadIdx.x) >> 5;
    int lane = threadIdx.x & 31;
    if (wid >= QSTAGES * KCB) return;
    const float* row = cb + (size_t)wid * DIM;
    double s = 0.0;
#pragma unroll
    for (int i = 0; i < 4; i++) {
        double v = (double)row[lane + i * 32];
        s = fma(v, v, s);
    }
#pragma unroll
    for (int off = 16; off; off >>= 1) s += __shfl_down_sync(0xffffffffu, s, off);
    if (lane == 0) g_enorm[wid] = (float)s;
}

// ---------------------------------------------------------------------------
// One RVQ stage. 512 threads, 256x128 tile. Warp = (row-half, 16-cw group);
// thread = 4 rows x 16 cw. Acc u64s pack CW-PAIRS: B fragments are natural
// u64s from warp-uniform LDS.128 (1 phase each); A is one lane-consecutive
// LDS.128 (zero-waste) + 4 dup movs. Conflict-free smem stores.
// ---------------------------------------------------------------------------
struct MM { float A[2][8][260]; float B[2][8][132]; };

template <int STAGE>
__global__ __launch_bounds__(NTHR, 1)
void rvq_stage_kernel(const float* __restrict__ x,
                      const float* __restrict__ cbq,
                      float* __restrict__ out)
{
    const float* cb  = cbq + (size_t)STAGE * KCB * DIM;
    const float* rin = (STAGE == 0) ? x : (const float*)g_resid;

    __shared__ union { MM mm; u64 Red[256][9]; } sh;   // ~25 KB (overlaid)
    __shared__ float rrS[BROWS];
    __shared__ int   Ridx[BROWS];
    __shared__ int   Ridx2[BROWS];

    const int tid  = threadIdx.x;
    const int m0   = blockIdx.x * BROWS;
    const int lane = tid & 31;
    const int wrp  = tid >> 5;
    const int rh   = wrp >> 3;            // row half 0/1
    const int cwg  = wrp & 7;             // cw group 0..7 (16 cw each)
    const int rowb = rh * 128 + lane * 4; // first of this thread's 4 rows
    const int lrow = tid >> 1;            // loader row 0..255
    const int ld   = (tid & 1) * 4;       // loader dim offset {0,4}

    // ---- pre-pass: rr per row (double, correctly rounded) ----
    {
        const float* rv = rin + (size_t)(m0 + lrow) * DIM + (tid & 1) * 64;
        double s = 0.0;
#pragma unroll
        for (int c = 0; c < 16; c++) {
            float4 v = *(const float4*)(rv + c * 4);
            s = fma((double)v.x, (double)v.x, s);
            s = fma((double)v.y, (double)v.y, s);
            s = fma((double)v.z, (double)v.z, s);
            s = fma((double)v.w, (double)v.w, s);
        }
        s += __shfl_xor_sync(0xffffffffu, s, 1);
        if ((tid & 1) == 0) rrS[lrow] = (float)s;
    }
    __syncthreads();

    float rrv[4];
#pragma unroll
    for (int r = 0; r < 4; r++) rrv[r] = rrS[rowb + r];

    u64 best0 = UMAX64, best1 = UMAX64;   // per-row global top2 (tid<256)

    const float* aBase = rin + (size_t)(m0 + lrow) * DIM + ld;

    for (int nt = 0; nt < KCB / 128; nt++) {
        const int n0 = nt * 128;
        u64 acc2[4][8];                    // [row][cw-pair]
#pragma unroll
        for (int r = 0; r < 4; r++)
#pragma unroll
            for (int j = 0; j < 8; j++) acc2[r][j] = 0ull;

        const float* bBase = cb + (size_t)(n0 + lrow) * DIM + ld;

        __syncthreads();                   // Red readers done before overlay reuse
        // preload chunk 0 into buffer 0 (row-contiguous planes, conflict-free)
        {
            float4 a0 = *(const float4*)(aBase);
            sh.mm.A[0][ld + 0][lrow] = a0.x; sh.mm.A[0][ld + 1][lrow] = a0.y;
            sh.mm.A[0][ld + 2][lrow] = a0.z; sh.mm.A[0][ld + 3][lrow] = a0.w;
            if (tid < 256) {
                float4 b0 = *(const float4*)(bBase);
                sh.mm.B[0][ld + 0][lrow] = b0.x; sh.mm.B[0][ld + 1][lrow] = b0.y;
                sh.mm.B[0][ld + 2][lrow] = b0.z; sh.mm.B[0][ld + 3][lrow] = b0.w;
            }
        }
        __syncthreads();

#pragma unroll 1
        for (int ds = 0; ds < 16; ds++) {
            const int cur = ds & 1, nxt = cur ^ 1;
            float4 an, bn;
            if (ds < 15) {
                an = *(const float4*)(aBase + (ds + 1) * 8);
                if (tid < 256) bn = *(const float4*)(bBase + (ds + 1) * 8);
            }
#pragma unroll
            for (int dd = 0; dd < 8; dd++) {
                // A: one lane-consecutive LDS.128 (4 rows), dup via 4 movs
                float4 af = *(const float4*)&sh.mm.A[cur][dd][rowb];
                u64 ad[4] = { pack2f(af.x, af.x), pack2f(af.y, af.y),
                              pack2f(af.z, af.z), pack2f(af.w, af.w) };
                // B: 4 warp-uniform LDS.128 -> 8 natural cw-pair u64s
                const ulonglong2* bp =
                    (const ulonglong2*)&sh.mm.B[cur][dd][cwg * 16];
                ulonglong2 b0 = bp[0], b1 = bp[1], b2 = bp[2], b3 = bp[3];
                u64 bb[8] = { b0.x, b0.y, b1.x, b1.y, b2.x, b2.y, b3.x, b3.y };
#pragma unroll
                for (int r = 0; r < 4; r++)
#pragma unroll
                    for (int j = 0; j < 8; j++)
                        ffma2(acc2[r][j], ad[r], bb[j]);
            }
            if (ds < 15) {
                sh.mm.A[nxt][ld + 0][lrow] = an.x; sh.mm.A[nxt][ld + 1][lrow] = an.y;
                sh.mm.A[nxt][ld + 2][lrow] = an.z; sh.mm.A[nxt][ld + 3][lrow] = an.w;
                if (tid < 256) {
                    sh.mm.B[nxt][ld + 0][lrow] = bn.x; sh.mm.B[nxt][ld + 1][lrow] = bn.y;
                    sh.mm.B[nxt][ld + 2][lrow] = bn.z; sh.mm.B[nxt][ld + 3][lrow] = bn.w;
                }
                __syncthreads();
            }
        }

        // ---- scores replicate reference ((rr - 2*dot) + ee); local top2 ----
        float en[16];
#pragma unroll
        for (int j = 0; j < 16; j++)
            en[j] = __ldg(&g_enorm[STAGE * KCB + n0 + cwg * 16 + j]);

        u64 pb0[4], pb1[4];
#pragma unroll
        for (int r = 0; r < 4; r++) {
            u64 x0 = UMAX64, x1 = UMAX64;
#pragma unroll
            for (int j = 0; j < 8; j++) {
                float dlo, dhi;
                unpack2f(acc2[r][j], dlo, dhi);
                float slo = (rrv[r] - 2.0f * dlo) + en[2 * j];
                float shi = (rrv[r] - 2.0f * dhi) + en[2 * j + 1];
                unsigned idx = (unsigned)(n0 + cwg * 16 + 2 * j);
                top2(((u64)fkey(slo) << 32) | idx,       x0, x1);
                top2(((u64)fkey(shi) << 32) | (idx + 1), x0, x1);
            }
            pb0[r] = x0; pb1[r] = x1;
        }

        __syncthreads();   // A/B reads complete before Red overlays the buffers
#pragma unroll
        for (int r = 0; r < 4; r++) sh.Red[rowb + r][cwg] = pb0[r];
        __syncthreads();
        u64 t0 = UMAX64, t1 = UMAX64; int sstar = 0;
        if (tid < 256) {
#pragma unroll
            for (int t = 0; t < 8; t++) top2(sh.Red[tid][t], t0, t1);
            sstar = (int)((t0 & 127u) >> 4);   // winner cw-group
        }
        __syncthreads();
#pragma unroll
        for (int r = 0; r < 4; r++) sh.Red[rowb + r][cwg] = pb1[r];
        __syncthreads();
        if (tid < 256) {
            u64 w = sh.Red[tid][sstar];
            if (w < t1) t1 = w;
            top2(t0, best0, best1);
            top2(t1, best0, best1);
        }
    }

    __syncthreads();
    if (tid < 256) {
        Ridx[tid]  = (int)(best0 & 0xFFFFFFFFull);
        Ridx2[tid] = (int)(best1 & 0xFFFFFFFFull);
    }
    __syncthreads();

    // ---- double-precision rescue + residual update + loss ----
    const int row = tid >> 1;
    const int h   = (tid & 1) * 64;
    const int i1  = Ridx[row];
    const int i2  = Ridx2[row];
    const float* rv = rin + (size_t)(m0 + row) * DIM + h;
    const float* e1 = cb + (size_t)i1 * DIM + h;
    const float* e2 = cb + (size_t)i2 * DIM + h;

    double d1 = 0.0, d2 = 0.0;
#pragma unroll
    for (int c = 0; c < 16; c++) {
        float4 r4 = *(const float4*)(rv + c * 4);
        float4 q1 = *(const float4*)(e1 + c * 4);
        float4 q2 = *(const float4*)(e2 + c * 4);
        d1 = fma((double)r4.x, (double)q1.x, d1);
        d1 = fma((double)r4.y, (double)q1.y, d1);
        d1 = fma((double)r4.z, (double)q1.z, d1);
        d1 = fma((double)r4.w, (double)q1.w, d1);
        d2 = fma((double)r4.x, (double)q2.x, d2);
        d2 = fma((double)r4.y, (double)q2.y, d2);
        d2 = fma((double)r4.z, (double)q2.z, d2);
        d2 = fma((double)r4.w, (double)q2.w, d2);
    }
    d1 += __shfl_xor_sync(0xffffffffu, d1, 1);
    d2 += __shfl_xor_sync(0xffffffffu, d2, 1);

    const float rr = rrS[row];
    const float s1 = (rr - 2.0f * (float)d1) + __ldg(&g_enorm[STAGE * KCB + i1]);
    const float s2 = (rr - 2.0f * (float)d2) + __ldg(&g_enorm[STAGE * KCB + i2]);
    int cidx;
    if (s1 < s2)      cidx = i1;
    else if (s2 < s1) cidx = i2;
    else              cidx = (i1 < i2) ? i1 : i2;

    if ((tid & 1) == 0)
        out[(size_t)NROWS * DIM + 1 + (size_t)(m0 + row) * QSTAGES + STAGE] = (float)cidx;

    const float* qv = cb + (size_t)cidx * DIM + h;
    double lsum = 0.0;
#pragma unroll
    for (int c = 0; c < 16; c++) {
        float4 q = *(const float4*)(qv + c * 4);
        float4 r = *(const float4*)(rv + c * 4);
        float4 rn;
        rn.x = r.x - q.x; rn.y = r.y - q.y; rn.z = r.z - q.z; rn.w = r.w - q.w;
        lsum += (double)rn.x * rn.x + (double)rn.y * rn.y +
                (double)rn.z * rn.z + (double)rn.w * rn.w;
        if (STAGE < QSTAGES - 1) {
            *(float4*)(g_resid + (size_t)(m0 + row) * DIM + h + c * 4) = rn;
        } else {
            const float4 xx = *(const float4*)(x + (size_t)(m0 + row) * DIM + h + c * 4);
            float4 xq;
            xq.x = xx.x - rn.x; xq.y = xx.y - rn.y;
            xq.z = xx.z - rn.z; xq.w = xx.w - rn.w;
            *(float4*)(out + (size_t)(m0 + row) * DIM + h + c * 4) = xq;
        }
    }
#pragma unroll
    for (int off = 16; off; off >>= 1) lsum += __shfl_down_sync(0xffffffffu, lsum, off);
    if ((tid & 31) == 0) atomicAdd(&g_loss[STAGE], lsum);
}

// ---------------------------------------------------------------------------
__global__ void rvq_finalize_kernel(float* __restrict__ out) {
    if (threadIdx.x == 0) {
        double s = 0.0;
        for (int i = 0; i < QSTAGES; i++) s += g_loss[i];
        double mean = (1.0 + BETA) * s / ((double)NROWS * DIM) / (double)QSTAGES;
        out[(size_t)NROWS * DIM] = (float)mean;
    }
}

extern "C" void kernel_launch(void* const* d_in, const int* in_sizes, int n_in,
                              void* d_out, int out_size) {
    const float* x  = (const float*)d_in[0];
    const float* cb = (const float*)d_in[1];
    if (n_in >= 2 && in_sizes[0] == QSTAGES * KCB * DIM && in_sizes[1] == NROWS * DIM) {
        x  = (const float*)d_in[1];
        cb = (const float*)d_in[0];
    }
    float* out = (float*)d_out;

    rvq_prep_kernel<<<512, 256>>>(cb);
    rvq_stage_kernel<0><<<NROWS / BROWS, NTHR>>>(x, cb, out);
    rvq_stage_kernel<1><<<NROWS / BROWS, NTHR>>>(x, cb, out);
    rvq_stage_kernel<2><<<NROWS / BROWS, NTHR>>>(x, cb, out);
    rvq_stage_kernel<3><<<NROWS / BROWS, NTHR>>>(x, cb, out);
    rvq_finalize_kernel<<<1, 32>>>(out);
}

// round 7
// speedup vs baseline: 2.5848x; 1.2740x over previous
#include <cuda_runtime.h>
#include <stdint.h>

#define NROWS   131072
#define DIM     128
#define QSTAGES 4
#define KCB     1024
#define BETA    0.25
#define BROWS   128            // rows per block
#define NTHR    256
#define CH      16             // dims per smem chunk
#define NCH     (DIM / CH)     // 8 chunks

typedef unsigned long long u64;
#define UMAX64 0xFFFFFFFFFFFFFFFFull

// Scratch (allocation-free rule: __device__ globals)
__device__ float  g_resid[NROWS * DIM];
__device__ float  g_enorm[QSTAGES * KCB];
__device__ double g_loss[QSTAGES];

// ---------------------------------------------------------------------------
// packed fp32x2 helpers (Blackwell sm_100+)
// ---------------------------------------------------------------------------
__device__ __forceinline__ u64 pack2f(float lo, float hi) {
    u64 r; asm("mov.b64 %0, {%1, %2};" : "=l"(r) : "f"(lo), "f"(hi)); return r;
}
__device__ __forceinline__ void unpack2f(u64 v, float& lo, float& hi) {
    asm("mov.b64 {%0, %1}, %2;" : "=f"(lo), "=f"(hi) : "l"(v));
}
__device__ __forceinline__ void ffma2(u64& d, u64 a, u64 b) {
    asm("fma.rn.f32x2 %0, %1, %2, %0;" : "+l"(d) : "l"(a), "l"(b));
}
__device__ __forceinline__ unsigned int fkey(float f) {
    unsigned int u = __float_as_uint(f);
    return (u & 0x80000000u) ? ~u : (u | 0x80000000u);
}
__device__ __forceinline__ void top2(u64 k, u64& b0, u64& b1) {
    if (k < b0) { b1 = b0; b0 = k; }
    else if (k < b1) { b1 = k; }
}

// ---------------------------------------------------------------------------
__global__ void rvq_prep_kernel(const float* __restrict__ cb) {
    if (blockIdx.x == 0 && threadIdx.x < QSTAGES) g_loss[threadIdx.x] = 0.0;
    int wid  = (blockIdx.x * blockDim.x + threadIdx.x) >> 5;
    int lane = threadIdx.x & 31;
    if (wid >= QSTAGES * KCB) return;
    const float* row = cb + (size_t)wid * DIM;
    double s = 0.0;
#pragma unroll
    for (int i = 0; i < 4; i++) {
        double v = (double)row[lane + i * 32];
        s = fma(v, v, s);
    }
#pragma unroll
    for (int off = 16; off; off >>= 1) s += __shfl_down_sync(0xffffffffu, s, off);
    if (lane == 0) g_enorm[wid] = (float)s;
}

// ---------------------------------------------------------------------------
// One RVQ stage. 256 threads, 128x128 tile, 2 blocks/SM. Warp = one 16-cw
// group x all 128 rows; thread = 4 rows x 16 cw. Accumulators pack CW-PAIRS
// so B fragments are natural u64s from 4 warp-uniform LDS.128 (1 phase each)
// and A is one lane-consecutive LDS.128 (full-width) + 4 dup movs.
// 16-dim chunks, double-buffered: 1 sync per chunk.
// ---------------------------------------------------------------------------
template <int STAGE>
__global__ __launch_bounds__(NTHR, 2)
void rvq_stage_kernel(const float* __restrict__ x,
                      const float* __restrict__ cbq,
                      float* __restrict__ out)
{
    const float* cb  = cbq + (size_t)STAGE * KCB * DIM;
    const float* rin = (STAGE == 0) ? x : (const float*)g_resid;

    __shared__ __align__(16) float As[2][CH][132];  // 16.9 KB
    __shared__ __align__(16) float Bs[2][CH][132];  // 16.9 KB
    __shared__ u64   Red[BROWS][9];                 //  9.2 KB
    __shared__ float rrS[BROWS];
    __shared__ int   Ridx[BROWS];
    __shared__ int   Ridx2[BROWS];

    const int tid  = threadIdx.x;
    const int m0   = blockIdx.x * BROWS;
    const int lane = tid & 31;
    const int cwg  = tid >> 5;            // warp id = cw group 0..7 (16 cw each)
    const int rowb = lane * 4;            // first of this thread's 4 rows
    const int lrow = tid & 127;           // loader row / cw
    const int lh   = (tid >> 7) * 8;      // loader dim offset {0,8}

    // ---- pre-pass: rr per row (double, correctly rounded) ----
    {
        const int row = tid >> 1;
        const float* rv = rin + (size_t)(m0 + row) * DIM + (tid & 1) * 64;
        double s = 0.0;
#pragma unroll
        for (int c = 0; c < 16; c++) {
            float4 v = *(const float4*)(rv + c * 4);
            s = fma((double)v.x, (double)v.x, s);
            s = fma((double)v.y, (double)v.y, s);
            s = fma((double)v.z, (double)v.z, s);
            s = fma((double)v.w, (double)v.w, s);
        }
        s += __shfl_xor_sync(0xffffffffu, s, 1);
        if ((tid & 1) == 0) rrS[row] = (float)s;
    }
    __syncthreads();

    float rrv[4];
#pragma unroll
    for (int r = 0; r < 4; r++) rrv[r] = rrS[rowb + r];

    u64 best0 = UMAX64, best1 = UMAX64;   // per-row global top2 (tid<128: row=tid)

    const float* aBase = rin + (size_t)(m0 + lrow) * DIM + lh;

    for (int nt = 0; nt < KCB / 128; nt++) {
        const int n0 = nt * 128;
        u64 acc2[4][8];                    // [row][cw-pair]
#pragma unroll
        for (int r = 0; r < 4; r++)
#pragma unroll
            for (int j = 0; j < 8; j++) acc2[r][j] = 0ull;

        const float* bBase = cb + (size_t)(n0 + lrow) * DIM + lh;

        __syncthreads();                   // Red pass-2 readers done (prior nt)
        // preload chunk 0 into buffer 0 (row-contiguous planes, conflict-free)
        {
            float4 a0 = *(const float4*)(aBase);
            float4 a1 = *(const float4*)(aBase + 4);
            float4 b0 = *(const float4*)(bBase);
            float4 b1 = *(const float4*)(bBase + 4);
            As[0][lh + 0][lrow] = a0.x; As[0][lh + 1][lrow] = a0.y;
            As[0][lh + 2][lrow] = a0.z; As[0][lh + 3][lrow] = a0.w;
            As[0][lh + 4][lrow] = a1.x; As[0][lh + 5][lrow] = a1.y;
            As[0][lh + 6][lrow] = a1.z; As[0][lh + 7][lrow] = a1.w;
            Bs[0][lh + 0][lrow] = b0.x; Bs[0][lh + 1][lrow] = b0.y;
            Bs[0][lh + 2][lrow] = b0.z; Bs[0][lh + 3][lrow] = b0.w;
            Bs[0][lh + 4][lrow] = b1.x; Bs[0][lh + 5][lrow] = b1.y;
            Bs[0][lh + 6][lrow] = b1.z; Bs[0][lh + 7][lrow] = b1.w;
        }
        __syncthreads();

#pragma unroll 1
        for (int ds = 0; ds < NCH; ds++) {
            const int cur = ds & 1, nxt = cur ^ 1;
            float4 an0, an1, bn0, bn1;
            if (ds < NCH - 1) {
                an0 = *(const float4*)(aBase + (ds + 1) * CH);
                an1 = *(const float4*)(aBase + (ds + 1) * CH + 4);
                bn0 = *(const float4*)(bBase + (ds + 1) * CH);
                bn1 = *(const float4*)(bBase + (ds + 1) * CH + 4);
            }
#pragma unroll
            for (int dd = 0; dd < CH; dd++) {
                // A: one lane-consecutive LDS.128 (4 rows), dup via 4 movs
                float4 af = *(const float4*)&As[cur][dd][rowb];
                u64 ad[4] = { pack2f(af.x, af.x), pack2f(af.y, af.y),
                              pack2f(af.z, af.z), pack2f(af.w, af.w) };
                // B: 4 warp-uniform LDS.128 -> 8 natural cw-pair u64s
                const ulonglong2* bp = (const ulonglong2*)&Bs[cur][dd][cwg * 16];
                ulonglong2 b0 = bp[0], b1 = bp[1], b2 = bp[2], b3 = bp[3];
                u64 bb[8] = { b0.x, b0.y, b1.x, b1.y, b2.x, b2.y, b3.x, b3.y };
#pragma unroll
                for (int r = 0; r < 4; r++)
#pragma unroll
                    for (int j = 0; j < 8; j++)
                        ffma2(acc2[r][j], ad[r], bb[j]);
            }
            if (ds < NCH - 1) {
                As[nxt][lh + 0][lrow] = an0.x; As[nxt][lh + 1][lrow] = an0.y;
                As[nxt][lh + 2][lrow] = an0.z; As[nxt][lh + 3][lrow] = an0.w;
                As[nxt][lh + 4][lrow] = an1.x; As[nxt][lh + 5][lrow] = an1.y;
                As[nxt][lh + 6][lrow] = an1.z; As[nxt][lh + 7][lrow] = an1.w;
                Bs[nxt][lh + 0][lrow] = bn0.x; Bs[nxt][lh + 1][lrow] = bn0.y;
                Bs[nxt][lh + 2][lrow] = bn0.z; Bs[nxt][lh + 3][lrow] = bn0.w;
                Bs[nxt][lh + 4][lrow] = bn1.x; Bs[nxt][lh + 5][lrow] = bn1.y;
                Bs[nxt][lh + 6][lrow] = bn1.z; Bs[nxt][lh + 7][lrow] = bn1.w;
                __syncthreads();
            }
        }

        // ---- scores replicate reference ((rr - 2*dot) + ee); local top2 ----
        float en[16];
#pragma unroll
        for (int j = 0; j < 16; j++)
            en[j] = __ldg(&g_enorm[STAGE * KCB + n0 + cwg * 16 + j]);

        u64 pb0[4], pb1[4];
#pragma unroll
        for (int r = 0; r < 4; r++) {
            u64 x0 = UMAX64, x1 = UMAX64;
#pragma unroll
            for (int j = 0; j < 8; j++) {
                float dlo, dhi;
                unpack2f(acc2[r][j], dlo, dhi);
                float slo = (rrv[r] - 2.0f * dlo) + en[2 * j];
                float shi = (rrv[r] - 2.0f * dhi) + en[2 * j + 1];
                unsigned idx = (unsigned)(n0 + cwg * 16 + 2 * j);
                top2(((u64)fkey(slo) << 32) | idx,       x0, x1);
                top2(((u64)fkey(shi) << 32) | (idx + 1), x0, x1);
            }
            pb0[r] = x0; pb1[r] = x1;
        }

        // pass 1: per-stripe top1s -> global top1 t0 + 2nd-min-of-b0s t1
        __syncthreads();   // mainloop smem reads done; Red safe to write
#pragma unroll
        for (int r = 0; r < 4; r++) Red[rowb + r][cwg] = pb0[r];
        __syncthreads();
        u64 t0 = UMAX64, t1 = UMAX64; int sstar = 0;
        if (tid < 128) {
#pragma unroll
            for (int t = 0; t < 8; t++) top2(Red[tid][t], t0, t1);
            sstar = (int)((t0 & 127u) >> 4);   // winner cw-group
        }
        __syncthreads();
        // pass 2: per-stripe runner-ups; exact top2 = min(t1, b1[winner])
#pragma unroll
        for (int r = 0; r < 4; r++) Red[rowb + r][cwg] = pb1[r];
        __syncthreads();
        if (tid < 128) {
            u64 w = Red[tid][sstar];
            if (w < t1) t1 = w;
            top2(t0, best0, best1);
            top2(t1, best0, best1);
        }
    }

    __syncthreads();
    if (tid < 128) {
        Ridx[tid]  = (int)(best0 & 0xFFFFFFFFull);
        Ridx2[tid] = (int)(best1 & 0xFFFFFFFFull);
    }
    __syncthreads();

    // ---- double-precision rescue + residual update + loss ----
    const int row = tid >> 1;
    const int h   = (tid & 1) * 64;
    const int i1  = Ridx[row];
    const int i2  = Ridx2[row];
    const float* rv = rin + (size_t)(m0 + row) * DIM + h;
    const float* e1 = cb + (size_t)i1 * DIM + h;
    const float* e2 = cb + (size_t)i2 * DIM + h;

    double d1 = 0.0, d2 = 0.0;
#pragma unroll
    for (int c = 0; c < 16; c++) {
        float4 r4 = *(const float4*)(rv + c * 4);
        float4 q1 = *(const float4*)(e1 + c * 4);
        float4 q2 = *(const float4*)(e2 + c * 4);
        d1 = fma((double)r4.x, (double)q1.x, d1);
        d1 = fma((double)r4.y, (double)q1.y, d1);
        d1 = fma((double)r4.z, (double)q1.z, d1);
        d1 = fma((double)r4.w, (double)q1.w, d1);
        d2 = fma((double)r4.x, (double)q2.x, d2);
        d2 = fma((double)r4.y, (double)q2.y, d2);
        d2 = fma((double)r4.z, (double)q2.z, d2);
        d2 = fma((double)r4.w, (double)q2.w, d2);
    }
    d1 += __shfl_xor_sync(0xffffffffu, d1, 1);
    d2 += __shfl_xor_sync(0xffffffffu, d2, 1);

    const float rr = rrS[row];
    const float s1 = (rr - 2.0f * (float)d1) + __ldg(&g_enorm[STAGE * KCB + i1]);
    const float s2 = (rr - 2.0f * (float)d2) + __ldg(&g_enorm[STAGE * KCB + i2]);
    int cidx;
    if (s1 < s2)      cidx = i1;
    else if (s2 < s1) cidx = i2;
    else              cidx = (i1 < i2) ? i1 : i2;

    if ((tid & 1) == 0)
        out[(size_t)NROWS * DIM + 1 + (size_t)(m0 + row) * QSTAGES + STAGE] = (float)cidx;

    const float* qv = cb + (size_t)cidx * DIM + h;
    double lsum = 0.0;
#pragma unroll
    for (int c = 0; c < 16; c++) {
        float4 q = *(const float4*)(qv + c * 4);
        float4 r = *(const float4*)(rv + c * 4);
        float4 rn;
        rn.x = r.x - q.x; rn.y = r.y - q.y; rn.z = r.z - q.z; rn.w = r.w - q.w;
        lsum += (double)rn.x * rn.x + (double)rn.y * rn.y +
                (double)rn.z * rn.z + (double)rn.w * rn.w;
        if (STAGE < QSTAGES - 1) {
            *(float4*)(g_resid + (size_t)(m0 + row) * DIM + h + c * 4) = rn;
        } else {
            const float4 xx = *(const float4*)(x + (size_t)(m0 + row) * DIM + h + c * 4);
            float4 xq;
            xq.x = xx.x - rn.x; xq.y = xx.y - rn.y;
            xq.z = xx.z - rn.z; xq.w = xx.w - rn.w;
            *(float4*)(out + (size_t)(m0 + row) * DIM + h + c * 4) = xq;
        }
    }
#pragma unroll
    for (int off = 16; off; off >>= 1) lsum += __shfl_down_sync(0xffffffffu, lsum, off);
    if ((tid & 31) == 0) atomicAdd(&g_loss[STAGE], lsum);
}

// ---------------------------------------------------------------------------
__global__ void rvq_finalize_kernel(float* __restrict__ out) {
    if (threadIdx.x == 0) {
        double s = 0.0;
        for (int i = 0; i < QSTAGES; i++) s += g_loss[i];
        double mean = (1.0 + BETA) * s / ((double)NROWS * DIM) / (double)QSTAGES;
        out[(size_t)NROWS * DIM] = (float)mean;
    }
}

extern "C" void kernel_launch(void* const* d_in, const int* in_sizes, int n_in,
                              void* d_out, int out_size) {
    const float* x  = (const float*)d_in[0];
    const float* cb = (const float*)d_in[1];
    if (n_in >= 2 && in_sizes[0] == QSTAGES * KCB * DIM && in_sizes[1] == NROWS * DIM) {
        x  = (const float*)d_in[1];
        cb = (const float*)d_in[0];
    }
    float* out = (float*)d_out;

    rvq_prep_kernel<<<512, 256>>>(cb);
    rvq_stage_kernel<0><<<NROWS / BROWS, NTHR>>>(x, cb, out);
    rvq_stage_kernel<1><<<NROWS / BROWS, NTHR>>>(x, cb, out);
    rvq_stage_kernel<2><<<NROWS / BROWS, NTHR>>>(x, cb, out);
    rvq_stage_kernel<3><<<NROWS / BROWS, NTHR>>>(x, cb, out);
    rvq_finalize_kernel<<<1, 32>>>(out);
}